// round 1
// baseline (speedup 1.0000x reference)
#include <cuda_runtime.h>
#include <cuda_bf16.h>

// Trajectory signature kernel.
// Input:  trajectories [4096, 2048, 6] fp32 (row-major)
// Output: [4096, 5] fp32: {path_curvature, velocity_smoothness,
//                          acceleration_jerk, movement_rhythm, force_modulation}
//
// Insight: positions = cumsum(traj[:,:2]); v1/v2 are diffs of positions,
// i.e. just the raw col-0/1 values. Everything is a consecutive-row-pair
// reduction -> one CTA per trajectory, lane==row, shfl_up for prev row.

#define T_LEN   2048
#define N_TRAJ  4096
#define EPS_NORM 1e-6f
#define EPS_MEAN 1e-6f

__device__ __forceinline__ float warp_sum(float x) {
    #pragma unroll
    for (int o = 16; o > 0; o >>= 1)
        x += __shfl_down_sync(0xffffffffu, x, o);
    return x;
}

__global__ __launch_bounds__(256) void signature_kernel(
    const float* __restrict__ traj, float* __restrict__ out)
{
    const int tr   = blockIdx.x;
    const int lane = threadIdx.x & 31;
    const int wid  = threadIdx.x >> 5;

    const float* base = traj + (size_t)tr * (T_LEN * 6);

    float s_curv = 0.f, cnt = 0.f;
    float s_vd = 0.f, s_ad = 0.f;
    float s_sp = 0.f, s_sp2 = 0.f;
    float s_f  = 0.f, s_f2  = 0.f;

    // 2048 rows / 32 lanes = 64 chunks; 8 warps -> 8 chunks per warp.
    #pragma unroll
    for (int c = 0; c < (T_LEN / 32) / 8; ++c) {
        const int chunk = c * 8 + wid;
        const int r = chunk * 32 + lane;
        const float* rowp = base + r * 6;

        const float2 p = *reinterpret_cast<const float2*>(rowp);      // cols 0,1
        const float2 v = *reinterpret_cast<const float2*>(rowp + 2);  // cols 2,3
        const float2 a = *reinterpret_cast<const float2*>(rowp + 4);  // cols 4,5

        // per-row moments
        const float speed = sqrtf(v.x * v.x + v.y * v.y);
        const float force = sqrtf(a.x * a.x + a.y * a.y);
        s_sp  += speed;  s_sp2 += speed * speed;
        s_f   += force;  s_f2  += force * force;

        const float pn = sqrtf(p.x * p.x + p.y * p.y);  // |pos-delta| for this row

        // previous row's values via shuffle (lane 0 loads the boundary row)
        float ppx = __shfl_up_sync(0xffffffffu, p.x, 1);
        float ppy = __shfl_up_sync(0xffffffffu, p.y, 1);
        float pvx = __shfl_up_sync(0xffffffffu, v.x, 1);
        float pvy = __shfl_up_sync(0xffffffffu, v.y, 1);
        float pax = __shfl_up_sync(0xffffffffu, a.x, 1);
        float pay = __shfl_up_sync(0xffffffffu, a.y, 1);
        float ppn = __shfl_up_sync(0xffffffffu, pn, 1);

        if (lane == 0 && r > 0) {
            const float* prow = rowp - 6;
            const float2 pp = *reinterpret_cast<const float2*>(prow);
            const float2 pv = *reinterpret_cast<const float2*>(prow + 2);
            const float2 pa = *reinterpret_cast<const float2*>(prow + 4);
            ppx = pp.x; ppy = pp.y;
            pvx = pv.x; pvy = pv.y;
            pax = pa.x; pay = pa.y;
            ppn = sqrtf(ppx * ppx + ppy * ppy);
        }

        if (r >= 1) {
            s_vd += fabsf(v.x - pvx) + fabsf(v.y - pvy);
            s_ad += fabsf(a.x - pax) + fabsf(a.y - pay);
        }
        if (r >= 2) {
            // v1 = row r-1 cols 0:2, v2 = row r cols 0:2
            const float crossv = ppx * p.y - ppy * p.x;
            const float n = ppn * pn;
            if (n > EPS_NORM) {
                s_curv += fabsf(crossv) / n;
                cnt += 1.0f;
            }
        }
    }

    // intra-warp reduce
    s_curv = warp_sum(s_curv);
    cnt    = warp_sum(cnt);
    s_vd   = warp_sum(s_vd);
    s_ad   = warp_sum(s_ad);
    s_sp   = warp_sum(s_sp);
    s_sp2  = warp_sum(s_sp2);
    s_f    = warp_sum(s_f);
    s_f2   = warp_sum(s_f2);

    __shared__ float red[8][8];
    if (lane == 0) {
        red[wid][0] = s_curv; red[wid][1] = cnt;
        red[wid][2] = s_vd;   red[wid][3] = s_ad;
        red[wid][4] = s_sp;   red[wid][5] = s_sp2;
        red[wid][6] = s_f;    red[wid][7] = s_f2;
    }
    __syncthreads();

    if (threadIdx.x == 0) {
        float t_curv = 0.f, t_cnt = 0.f, t_vd = 0.f, t_ad = 0.f;
        float t_sp = 0.f, t_sp2 = 0.f, t_f = 0.f, t_f2 = 0.f;
        #pragma unroll
        for (int w = 0; w < 8; ++w) {
            t_curv += red[w][0]; t_cnt += red[w][1];
            t_vd   += red[w][2]; t_ad  += red[w][3];
            t_sp   += red[w][4]; t_sp2 += red[w][5];
            t_f    += red[w][6]; t_f2  += red[w][7];
        }

        const float path_curvature = (t_cnt > 0.f) ? (t_curv / t_cnt) : 0.f;

        const float denom = 2.0f * (float)(T_LEN - 1);  // (T-1) pairs x 2 comps
        const float velocity_smoothness = 1.0f / (1.0f + t_vd / denom);
        const float acceleration_jerk   = t_ad / denom;

        const float msp  = t_sp / (float)T_LEN;
        float var_sp = t_sp2 / (float)T_LEN - msp * msp;
        if (var_sp < 0.f) var_sp = 0.f;
        const float movement_rhythm = sqrtf(var_sp) / (msp + EPS_MEAN);

        const float mf = t_f / (float)T_LEN;
        float var_f = t_f2 / (float)T_LEN - mf * mf;
        if (var_f < 0.f) var_f = 0.f;
        const float force_modulation = sqrtf(var_f) / (mf + EPS_MEAN);

        float* o = out + tr * 5;
        o[0] = path_curvature;
        o[1] = velocity_smoothness;
        o[2] = acceleration_jerk;
        o[3] = movement_rhythm;
        o[4] = force_modulation;
    }
}

extern "C" void kernel_launch(void* const* d_in, const int* in_sizes, int n_in,
                              void* d_out, int out_size) {
    const float* traj = (const float*)d_in[0];
    float* out = (float*)d_out;
    signature_kernel<<<N_TRAJ, 256>>>(traj, out);
}

// round 5
// speedup vs baseline: 1.0363x; 1.0363x over previous
#include <cuda_runtime.h>
#include <cuda_bf16.h>

// Trajectory signature kernel, v2.1: smem tile staging + rsqrt curvature.
// Input:  trajectories [4096, 2048, 6] fp32 (row-major)
// Output: [4096, 5] fp32
//
// positions = cumsum(traj[:,:2]) and v1/v2 are diffs of it, i.e. the raw
// col 0:2 values -> everything is a consecutive-row-pair reduction.
// One CTA per trajectory. Tiles of 512 rows are loaded with coalesced
// float4s into a stride-7 padded smem buffer (conflict-free LDS), double
// buffered so tile t+1 global loads overlap tile t compute.

#define T_LEN   2048
#define N_TRAJ  4096
#define TILE    512
#define NT      (T_LEN / TILE)            // 4
#define F4_PER_TILE (TILE * 6 / 4)        // 768
#define ROW_PAD 7
#define BUF_WORDS ((TILE + 1) * ROW_PAD)  // prev-row slot at words [0..5]
#define EPS_NORM 1e-6f
#define EPS_MEAN 1e-6f

__device__ __forceinline__ float warp_sum(float x) {
    #pragma unroll
    for (int o = 16; o > 0; o >>= 1)
        x += __shfl_down_sync(0xffffffffu, x, o);
    return x;
}

// tile word w (row w/6, col w%6) -> padded smem address (+ROW_PAD skips prev slot)
__device__ __forceinline__ int paddr(int w) {
    return ROW_PAD + (w / 6) * ROW_PAD + (w % 6);
}

__device__ __forceinline__ void store_f4(float* buf, int f4idx, float4 v) {
    const int w = f4idx * 4;
    buf[paddr(w + 0)] = v.x;
    buf[paddr(w + 1)] = v.y;
    buf[paddr(w + 2)] = v.z;
    buf[paddr(w + 3)] = v.w;
}

__global__ __launch_bounds__(256) void signature_kernel(
    const float4* __restrict__ trajv, float* __restrict__ out)
{
    __shared__ float sb[2][BUF_WORDS];

    const int tid = threadIdx.x;
    const int tr  = blockIdx.x;
    const float4* base = trajv + (size_t)tr * (T_LEN * 6 / 4);

    float s_curv = 0.f, cnt = 0.f;
    float s_vd = 0.f, s_ad = 0.f;
    float s_sp = 0.f, s_sp2 = 0.f;
    float s_f  = 0.f, s_f2  = 0.f;

    // prologue: tile 0 -> buf 0
    {
        float4 q0 = base[tid];
        float4 q1 = base[tid + 256];
        float4 q2 = base[tid + 512];
        store_f4(sb[0], tid,       q0);
        store_f4(sb[0], tid + 256, q1);
        store_f4(sb[0], tid + 512, q2);
    }

    #pragma unroll
    for (int t = 0; t < NT; ++t) {
        const int cur = t & 1;
        const int nxt = cur ^ 1;

        // prefetch next tile into registers (overlaps with compute below)
        float4 p0, p1, p2;
        if (t < NT - 1) {
            const float4* nb = base + (t + 1) * F4_PER_TILE;
            p0 = nb[tid];
            p1 = nb[tid + 256];
            p2 = nb[tid + 512];
        }

        __syncthreads();  // buf[cur] fully stored; buf[nxt] readers done

        // compute: 512 rows, 2 rows per thread (stride-256 sub-iterations)
        #pragma unroll
        for (int s = 0; s < 2; ++s) {
            const int lr = s * 256 + tid;         // local row in tile
            const int r  = t * TILE + lr;         // global row
            const float* curp = &sb[cur][(lr + 1) * ROW_PAD];
            const float* prvp = &sb[cur][lr * ROW_PAD];  // lr==0 -> prev slot

            const float px = curp[0], py = curp[1];
            const float vx = curp[2], vy = curp[3];
            const float ax = curp[4], ay = curp[5];

            const float speed = sqrtf(vx * vx + vy * vy);
            const float force = sqrtf(ax * ax + ay * ay);
            s_sp += speed; s_sp2 += speed * speed;
            s_f  += force; s_f2  += force * force;

            if (r >= 1) {
                const float ppx = prvp[0], ppy = prvp[1];
                const float pvx = prvp[2], pvy = prvp[3];
                const float pax = prvp[4], pay = prvp[5];

                s_vd += fabsf(vx - pvx) + fabsf(vy - pvy);
                s_ad += fabsf(ax - pax) + fabsf(ay - pay);

                if (r >= 2) {
                    // |cross|/(|v1||v2|) with mask n>EPS  ==
                    // |cross|*rsqrt(n1sq*n2sq) with mask n1sq*n2sq>EPS^2
                    const float n2sq = px * px + py * py;
                    const float n1sq = ppx * ppx + ppy * ppy;
                    const float prod = n1sq * n2sq;
                    const float crossv = ppx * py - ppy * px;
                    if (prod > EPS_NORM * EPS_NORM) {
                        s_curv += fabsf(crossv) * rsqrtf(prod);
                        cnt += 1.0f;
                    }
                }
            }
        }

        if (t < NT - 1) {
            // carry last row of this tile into next buffer's prev slot
            if (tid < 6)
                sb[nxt][tid] = sb[cur][TILE * ROW_PAD + tid];
            // publish prefetched tile (consumed after next iteration's sync)
            store_f4(sb[nxt], tid,       p0);
            store_f4(sb[nxt], tid + 256, p1);
            store_f4(sb[nxt], tid + 512, p2);
        }
    }

    // reductions
    s_curv = warp_sum(s_curv);
    cnt    = warp_sum(cnt);
    s_vd   = warp_sum(s_vd);
    s_ad   = warp_sum(s_ad);
    s_sp   = warp_sum(s_sp);
    s_sp2  = warp_sum(s_sp2);
    s_f    = warp_sum(s_f);
    s_f2   = warp_sum(s_f2);

    __shared__ float red[8][8];
    const int lane = tid & 31;
    const int wid  = tid >> 5;
    if (lane == 0) {
        red[wid][0] = s_curv; red[wid][1] = cnt;
        red[wid][2] = s_vd;   red[wid][3] = s_ad;
        red[wid][4] = s_sp;   red[wid][5] = s_sp2;
        red[wid][6] = s_f;    red[wid][7] = s_f2;
    }
    __syncthreads();

    if (tid == 0) {
        float t_curv = 0.f, t_cnt = 0.f, t_vd = 0.f, t_ad = 0.f;
        float t_sp = 0.f, t_sp2 = 0.f, t_f = 0.f, t_f2 = 0.f;
        #pragma unroll
        for (int w = 0; w < 8; ++w) {
            t_curv += red[w][0]; t_cnt += red[w][1];
            t_vd   += red[w][2]; t_ad  += red[w][3];
            t_sp   += red[w][4]; t_sp2 += red[w][5];
            t_f    += red[w][6]; t_f2  += red[w][7];
        }

        const float path_curvature = (t_cnt > 0.f) ? (t_curv / t_cnt) : 0.f;

        const float denom = 2.0f * (float)(T_LEN - 1);
        const float velocity_smoothness = 1.0f / (1.0f + t_vd / denom);
        const float acceleration_jerk   = t_ad / denom;

        const float msp = t_sp / (float)T_LEN;
        float var_sp = t_sp2 / (float)T_LEN - msp * msp;
        if (var_sp < 0.f) var_sp = 0.f;
        const float movement_rhythm = sqrtf(var_sp) / (msp + EPS_MEAN);

        const float mf = t_f / (float)T_LEN;
        float var_f = t_f2 / (float)T_LEN - mf * mf;
        if (var_f < 0.f) var_f = 0.f;
        const float force_modulation = sqrtf(var_f) / (mf + EPS_MEAN);

        float* o = out + tr * 5;
        o[0] = path_curvature;
        o[1] = velocity_smoothness;
        o[2] = acceleration_jerk;
        o[3] = movement_rhythm;
        o[4] = force_modulation;
    }
}

extern "C" void kernel_launch(void* const* d_in, const int* in_sizes, int n_in,
                              void* d_out, int out_size) {
    const float4* traj = (const float4*)d_in[0];
    float* out = (float*)d_out;
    signature_kernel<<<N_TRAJ, 256>>>(traj, out);
}

// round 7
// speedup vs baseline: 1.2871x; 1.2420x over previous
#include <cuda_runtime.h>
#include <cuda_bf16.h>
#include <cstdint>

// Trajectory signature kernel, v3.1: cp.async 2-deep pipeline, triple buffer.
// Input:  trajectories [4096, 2048, 6] fp32 (row-major)
// Output: [4096, 5] fp32
//
// positions = cumsum(traj[:,:2]); v1/v2 are diffs of it == raw col 0:2
// values -> everything is a consecutive-row-pair reduction.
// One CTA per trajectory. 4 tiles of 512 rows. cp.async streams tile t+2
// into smem while tile t is computed, keeping 2 tiles (24KB) in flight
// per CTA -> DRAM latency fully covered.

#define T_LEN   2048
#define N_TRAJ  4096
#define TILE    512
#define NT      (T_LEN / TILE)            // 4
#define F4_PER_TILE (TILE * 6 / 4)        // 768
#define HALO_W  8                         // halo words [2..7] hold prev row
#define BUF_WORDS (HALO_W + TILE * 6)     // 3080 words
#define EPS_NORM 1e-6f
#define EPS_MEAN 1e-6f

__device__ __forceinline__ float warp_sum(float x) {
    #pragma unroll
    for (int o = 16; o > 0; o >>= 1)
        x += __shfl_down_sync(0xffffffffu, x, o);
    return x;
}

__device__ __forceinline__ unsigned int smem_u32(const void* p) {
    unsigned int a;
    asm("{ .reg .u64 t; cvta.to.shared.u64 t, %1; cvt.u32.u64 %0, t; }"
        : "=r"(a) : "l"(p));
    return a;
}

#define CP_ASYNC16(dst_u32, src_ptr) \
    asm volatile("cp.async.cg.shared.global [%0], [%1], 16;" \
                 :: "r"(dst_u32), "l"(src_ptr) : "memory")
#define CP_COMMIT() asm volatile("cp.async.commit_group;" ::: "memory")
#define CP_WAIT(n)  asm volatile("cp.async.wait_group %0;" :: "n"(n) : "memory")

__global__ __launch_bounds__(256, 5) void signature_kernel(
    const float4* __restrict__ trajv, float* __restrict__ out)
{
    __shared__ __align__(16) float sb[3][BUF_WORDS];
    __shared__ float red[8][8];

    const int tid = threadIdx.x;
    const int tr  = blockIdx.x;
    const float4* base = trajv + (size_t)tr * (T_LEN * 6 / 4);

    // per-buffer smem byte address of float4 slot `tid` (word HALO_W + 4*tid)
    unsigned int dstb[3];
    #pragma unroll
    for (int b = 0; b < 3; ++b)
        dstb[b] = smem_u32(&sb[b][HALO_W + 4 * tid]);

    // prologue: issue tiles 0 and 1
    #pragma unroll
    for (int t = 0; t < 2; ++t) {
        const float4* src = base + t * F4_PER_TILE + tid;
        CP_ASYNC16(dstb[t],               src);
        CP_ASYNC16(dstb[t] + 256 * 16,    src + 256);
        CP_ASYNC16(dstb[t] + 512 * 16,    src + 512);
        CP_COMMIT();
    }

    float s_curv = 0.f, cnt = 0.f;
    float s_vd = 0.f, s_ad = 0.f;
    float s_sp = 0.f, s_sp2 = 0.f;
    float s_f  = 0.f, s_f2  = 0.f;

    #pragma unroll
    for (int t = 0; t < NT; ++t) {
        if (t == NT - 1) { CP_WAIT(0); } else { CP_WAIT(1); }
        __syncthreads();   // all threads' tile-t data visible; buf (t+2)%3 free

        const int cb = t % 3;

        // issue tile t+2 into buffer (t+2)%3 (overlaps compute below)
        if (t + 2 < NT) {
            const int nb2 = (t + 2) % 3;
            const float4* src = base + (t + 2) * F4_PER_TILE + tid;
            CP_ASYNC16(dstb[nb2],            src);
            CP_ASYNC16(dstb[nb2] + 256 * 16, src + 256);
            CP_ASYNC16(dstb[nb2] + 512 * 16, src + 512);
            CP_COMMIT();
        }

        // halo for tile t+1: copy last row of tile t into next buffer's halo
        if (t + 1 < NT && tid < 6)
            sb[(t + 1) % 3][2 + tid] = sb[cb][HALO_W + (TILE - 1) * 6 + tid];

        // compute tile t: 512 rows, 2 per thread
        #pragma unroll
        for (int s = 0; s < 2; ++s) {
            const int lr = s * 256 + tid;
            const int r  = t * TILE + lr;
            const float* curp = &sb[cb][HALO_W + lr * 6];
            const float* prvp = curp - 6;   // lr==0 -> halo words [2..7]

            const float px = curp[0], py = curp[1];
            const float vx = curp[2], vy = curp[3];
            const float ax = curp[4], ay = curp[5];

            const float speed = sqrtf(vx * vx + vy * vy);
            const float force = sqrtf(ax * ax + ay * ay);
            s_sp += speed; s_sp2 += speed * speed;
            s_f  += force; s_f2  += force * force;

            if (r >= 1) {
                const float ppx = prvp[0], ppy = prvp[1];
                const float pvx = prvp[2], pvy = prvp[3];
                const float pax = prvp[4], pay = prvp[5];

                s_vd += fabsf(vx - pvx) + fabsf(vy - pvy);
                s_ad += fabsf(ax - pax) + fabsf(ay - pay);

                if (r >= 2) {
                    // |cross|/(|v1||v2|), mask n>EPS == mask n1sq*n2sq>EPS^2
                    const float n2sq = px * px + py * py;
                    const float n1sq = ppx * ppx + ppy * ppy;
                    const float prod = n1sq * n2sq;
                    const float crossv = ppx * py - ppy * px;
                    if (prod > EPS_NORM * EPS_NORM) {
                        s_curv += fabsf(crossv) * rsqrtf(prod);
                        cnt += 1.0f;
                    }
                }
            }
        }
    }

    // reductions
    s_curv = warp_sum(s_curv);
    cnt    = warp_sum(cnt);
    s_vd   = warp_sum(s_vd);
    s_ad   = warp_sum(s_ad);
    s_sp   = warp_sum(s_sp);
    s_sp2  = warp_sum(s_sp2);
    s_f    = warp_sum(s_f);
    s_f2   = warp_sum(s_f2);

    const int lane = tid & 31;
    const int wid  = tid >> 5;
    if (lane == 0) {
        red[wid][0] = s_curv; red[wid][1] = cnt;
        red[wid][2] = s_vd;   red[wid][3] = s_ad;
        red[wid][4] = s_sp;   red[wid][5] = s_sp2;
        red[wid][6] = s_f;    red[wid][7] = s_f2;
    }
    __syncthreads();

    if (tid == 0) {
        float t_curv = 0.f, t_cnt = 0.f, t_vd = 0.f, t_ad = 0.f;
        float t_sp = 0.f, t_sp2 = 0.f, t_f = 0.f, t_f2 = 0.f;
        #pragma unroll
        for (int w = 0; w < 8; ++w) {
            t_curv += red[w][0]; t_cnt += red[w][1];
            t_vd   += red[w][2]; t_ad  += red[w][3];
            t_sp   += red[w][4]; t_sp2 += red[w][5];
            t_f    += red[w][6]; t_f2  += red[w][7];
        }

        const float path_curvature = (t_cnt > 0.f) ? (t_curv / t_cnt) : 0.f;

        const float denom = 2.0f * (float)(T_LEN - 1);
        const float velocity_smoothness = 1.0f / (1.0f + t_vd / denom);
        const float acceleration_jerk   = t_ad / denom;

        const float msp = t_sp / (float)T_LEN;
        float var_sp = t_sp2 / (float)T_LEN - msp * msp;
        if (var_sp < 0.f) var_sp = 0.f;
        const float movement_rhythm = sqrtf(var_sp) / (msp + EPS_MEAN);

        const float mf = t_f / (float)T_LEN;
        float var_f = t_f2 / (float)T_LEN - mf * mf;
        if (var_f < 0.f) var_f = 0.f;
        const float force_modulation = sqrtf(var_f) / (mf + EPS_MEAN);

        float* o = out + tr * 5;
        o[0] = path_curvature;
        o[1] = velocity_smoothness;
        o[2] = acceleration_jerk;
        o[3] = movement_rhythm;
        o[4] = force_modulation;
    }
}

extern "C" void kernel_launch(void* const* d_in, const int* in_sizes, int n_in,
                              void* d_out, int out_size) {
    const float4* traj = (const float4*)d_in[0];
    float* out = (float*)d_out;
    signature_kernel<<<N_TRAJ, 256>>>(traj, out);
}

// round 8
// speedup vs baseline: 1.3345x; 1.0369x over previous
#include <cuda_runtime.h>
#include <cuda_bf16.h>
#include <cstdint>

// Trajectory signature kernel, v4: cp.async pipeline + adjacent-row-pair
// compute (9x LDS.64/thread/tile) + 6 CTAs/SM.
// Input:  trajectories [4096, 2048, 6] fp32 (row-major)
// Output: [4096, 5] fp32
//
// positions = cumsum(traj[:,:2]); v1/v2 are diffs of it == raw col 0:2
// values -> everything is a consecutive-row-pair reduction.
// One CTA per trajectory. 4 tiles of 512 rows. cp.async streams tile t+2
// into smem while tile t is computed (2 tiles / 24KB in flight per CTA).
// Each thread processes rows 2*tid, 2*tid+1: one contiguous 18-word smem
// read covers prev row + both rows.

#define T_LEN   2048
#define N_TRAJ  4096
#define TILE    512
#define NT      (T_LEN / TILE)            // 4
#define F4_PER_TILE (TILE * 6 / 4)        // 768
#define HALO_W  8                         // halo words [2..7] hold prev row
#define BUF_WORDS (HALO_W + TILE * 6)     // 3080 words
#define EPS_NORM 1e-6f
#define EPS_MEAN 1e-6f

__device__ __forceinline__ float warp_sum(float x) {
    #pragma unroll
    for (int o = 16; o > 0; o >>= 1)
        x += __shfl_down_sync(0xffffffffu, x, o);
    return x;
}

__device__ __forceinline__ unsigned int smem_u32(const void* p) {
    unsigned int a;
    asm("{ .reg .u64 t; cvta.to.shared.u64 t, %1; cvt.u32.u64 %0, t; }"
        : "=r"(a) : "l"(p));
    return a;
}

#define CP_ASYNC16(dst_u32, src_ptr) \
    asm volatile("cp.async.cg.shared.global [%0], [%1], 16;" \
                 :: "r"(dst_u32), "l"(src_ptr) : "memory")
#define CP_COMMIT() asm volatile("cp.async.commit_group;" ::: "memory")
#define CP_WAIT(n)  asm volatile("cp.async.wait_group %0;" :: "n"(n) : "memory")

__global__ __launch_bounds__(256, 6) void signature_kernel(
    const float4* __restrict__ trajv, float* __restrict__ out)
{
    __shared__ __align__(16) float sb[3][BUF_WORDS];
    __shared__ float red[8][8];

    const int tid = threadIdx.x;
    const int tr  = blockIdx.x;
    const float4* base = trajv + (size_t)tr * (T_LEN * 6 / 4);

    // per-buffer smem byte address of float4 slot `tid` (word HALO_W + 4*tid)
    unsigned int dstb[3];
    #pragma unroll
    for (int b = 0; b < 3; ++b)
        dstb[b] = smem_u32(&sb[b][HALO_W + 4 * tid]);

    // prologue: issue tiles 0 and 1
    #pragma unroll
    for (int t = 0; t < 2; ++t) {
        const float4* src = base + t * F4_PER_TILE + tid;
        CP_ASYNC16(dstb[t],               src);
        CP_ASYNC16(dstb[t] + 256 * 16,    src + 256);
        CP_ASYNC16(dstb[t] + 512 * 16,    src + 512);
        CP_COMMIT();
    }

    float s_curv = 0.f, cnt = 0.f;
    float s_vd = 0.f, s_ad = 0.f;
    float s_sp = 0.f, s_sp2 = 0.f;
    float s_f  = 0.f, s_f2  = 0.f;

    #pragma unroll
    for (int t = 0; t < NT; ++t) {
        if (t == NT - 1) { CP_WAIT(0); } else { CP_WAIT(1); }
        __syncthreads();   // tile-t data visible to all; buf (t+2)%3 free

        const int cb = t % 3;

        // issue tile t+2 into buffer (t+2)%3 (overlaps compute below)
        if (t + 2 < NT) {
            const int nb2 = (t + 2) % 3;
            const float4* src = base + (t + 2) * F4_PER_TILE + tid;
            CP_ASYNC16(dstb[nb2],            src);
            CP_ASYNC16(dstb[nb2] + 256 * 16, src + 256);
            CP_ASYNC16(dstb[nb2] + 512 * 16, src + 512);
            CP_COMMIT();
        }

        // halo for tile t+1: copy last row of tile t into next buffer's halo
        if (t + 1 < NT && tid < 6)
            sb[(t + 1) % 3][2 + tid] = sb[cb][HALO_W + (TILE - 1) * 6 + tid];

        // compute: thread handles adjacent rows 2*tid, 2*tid+1.
        // 18 contiguous words: prev row | row0 | row1  (float2-aligned)
        const float2* rp = reinterpret_cast<const float2*>(
            &sb[cb][HALO_W + 12 * tid - 6]);   // tid==0 -> halo at words [2..7]
        const float2 pp = rp[0], pv = rp[1], pa = rp[2];   // prev row
        const float2 p0 = rp[3], v0 = rp[4], a0 = rp[5];   // row 2*tid
        const float2 p1 = rp[6], v1 = rp[7], a1 = rp[8];   // row 2*tid+1

        // per-row moments (both rows, always valid)
        const float sp0 = sqrtf(v0.x * v0.x + v0.y * v0.y);
        const float sp1 = sqrtf(v1.x * v1.x + v1.y * v1.y);
        const float fo0 = sqrtf(a0.x * a0.x + a0.y * a0.y);
        const float fo1 = sqrtf(a1.x * a1.x + a1.y * a1.y);
        s_sp  += sp0 + sp1;
        s_sp2 = fmaf(sp0, sp0, s_sp2); s_sp2 = fmaf(sp1, sp1, s_sp2);
        s_f   += fo0 + fo1;
        s_f2  = fmaf(fo0, fo0, s_f2);  s_f2  = fmaf(fo1, fo1, s_f2);

        const float nsq0 = p0.x * p0.x + p0.y * p0.y;
        const float nsq1 = p1.x * p1.x + p1.y * p1.y;

        // row1 <- row0 diffs (global r = 512t+2*tid+1 >= 1 always)
        s_vd += fabsf(v1.x - v0.x) + fabsf(v1.y - v0.y);
        s_ad += fabsf(a1.x - a0.x) + fabsf(a1.y - a0.y);

        const bool nf = (t > 0) | (tid > 0);   // rows 0/1 of trajectory excluded
        if (nf) {
            // row0 <- prev diffs
            s_vd += fabsf(v0.x - pv.x) + fabsf(v0.y - pv.y);
            s_ad += fabsf(a0.x - pa.x) + fabsf(a0.y - pa.y);

            // curvature row0 (v1=prev pos delta, v2=row0 pos delta)
            const float nsqp = pp.x * pp.x + pp.y * pp.y;
            const float cr0  = pp.x * p0.y - pp.y * p0.x;
            const float pr0  = nsqp * nsq0;
            if (pr0 > EPS_NORM * EPS_NORM) {
                s_curv = fmaf(fabsf(cr0), rsqrtf(pr0), s_curv);
                cnt += 1.0f;
            }
            // curvature row1
            const float cr1 = p0.x * p1.y - p0.y * p1.x;
            const float pr1 = nsq0 * nsq1;
            if (pr1 > EPS_NORM * EPS_NORM) {
                s_curv = fmaf(fabsf(cr1), rsqrtf(pr1), s_curv);
                cnt += 1.0f;
            }
        }
    }

    // reductions
    s_curv = warp_sum(s_curv);
    cnt    = warp_sum(cnt);
    s_vd   = warp_sum(s_vd);
    s_ad   = warp_sum(s_ad);
    s_sp   = warp_sum(s_sp);
    s_sp2  = warp_sum(s_sp2);
    s_f    = warp_sum(s_f);
    s_f2   = warp_sum(s_f2);

    const int lane = tid & 31;
    const int wid  = tid >> 5;
    if (lane == 0) {
        red[wid][0] = s_curv; red[wid][1] = cnt;
        red[wid][2] = s_vd;   red[wid][3] = s_ad;
        red[wid][4] = s_sp;   red[wid][5] = s_sp2;
        red[wid][6] = s_f;    red[wid][7] = s_f2;
    }
    __syncthreads();

    if (tid == 0) {
        float t_curv = 0.f, t_cnt = 0.f, t_vd = 0.f, t_ad = 0.f;
        float t_sp = 0.f, t_sp2 = 0.f, t_f = 0.f, t_f2 = 0.f;
        #pragma unroll
        for (int w = 0; w < 8; ++w) {
            t_curv += red[w][0]; t_cnt += red[w][1];
            t_vd   += red[w][2]; t_ad  += red[w][3];
            t_sp   += red[w][4]; t_sp2 += red[w][5];
            t_f    += red[w][6]; t_f2  += red[w][7];
        }

        const float path_curvature = (t_cnt > 0.f) ? (t_curv / t_cnt) : 0.f;

        const float denom = 2.0f * (float)(T_LEN - 1);
        const float velocity_smoothness = 1.0f / (1.0f + t_vd / denom);
        const float acceleration_jerk   = t_ad / denom;

        const float msp = t_sp / (float)T_LEN;
        float var_sp = t_sp2 / (float)T_LEN - msp * msp;
        if (var_sp < 0.f) var_sp = 0.f;
        const float movement_rhythm = sqrtf(var_sp) / (msp + EPS_MEAN);

        const float mf = t_f / (float)T_LEN;
        float var_f = t_f2 / (float)T_LEN - mf * mf;
        if (var_f < 0.f) var_f = 0.f;
        const float force_modulation = sqrtf(var_f) / (mf + EPS_MEAN);

        float* o = out + tr * 5;
        o[0] = path_curvature;
        o[1] = velocity_smoothness;
        o[2] = acceleration_jerk;
        o[3] = movement_rhythm;
        o[4] = force_modulation;
    }
}

extern "C" void kernel_launch(void* const* d_in, const int* in_sizes, int n_in,
                              void* d_out, int out_size) {
    const float4* traj = (const float4*)d_in[0];
    float* out = (float*)d_out;
    signature_kernel<<<N_TRAJ, 256>>>(traj, out);
}